// round 12
// baseline (speedup 1.0000x reference)
#include <cuda_runtime.h>
#include <cuda_bf16.h>
#include <cstdint>

#define S_LEN 2048
#define HID   512
#define IN_D  128
#define OUT_D 64
#define ALPHA 0.2f
#define NCS   8          // column-split CTAs per batch group
#define NGRP  16         // batch groups
#define NTHR  1024

typedef unsigned long long ull;

// ---- dynamic smem layout (float offsets) ----
#define H_ROW   520
#define H_BUF   (4 * H_ROW)                  // 2080
#define H_OFF   0                            // h[2][4][520]
#define X_OFF   (2 * H_BUF)                  // 4160 : x[2][512]
#define RED_ROW 264
#define RED_OFF (X_OFF + 2 * 512)            // 5184 : red[16][264]
#define WHO_ROW 520
#define WHO_OFF (RED_OFF + 16 * RED_ROW)     // 9408 : who[8][520]
#define WIH_OFF (WHO_OFF + 8 * WHO_ROW)      // 13568 : packed Wih, 4096 ull = 8192 floats
#define SMEM_FLOATS (WIH_OFF + 8192)         // 21760
#define SMEM_BYTES  (SMEM_FLOATS * 4)        // 87040

// L2-exchanged state
__device__ float    g_hbuf[2][64 * HID];
__device__ unsigned g_cnt[NGRP * 32];

// ---------------- packed f32x2 helpers ----------------
__device__ __forceinline__ ull fma2(ull a, ull b, ull c) {
    ull d;
    asm("fma.rn.f32x2 %0, %1, %2, %3;" : "=l"(d) : "l"(a), "l"(b), "l"(c));
    return d;
}
__device__ __forceinline__ ull pack2(float a, float b) {
    ull r;
    asm("mov.b64 %0, {%1, %2};" : "=l"(r) : "r"(__float_as_uint(a)), "r"(__float_as_uint(b)));
    return r;
}
__device__ __forceinline__ float lo2(ull v) { return __uint_as_float((unsigned)(v & 0xffffffffull)); }
__device__ __forceinline__ float hi2(ull v) { return __uint_as_float((unsigned)(v >> 32)); }
__device__ __forceinline__ float my_tanh(float v) {
    float e = __expf(2.0f * v);               // inf -> exactly +1, branch-free
    return 1.0f - __fdividef(2.0f, e + 1.0f);
}
__device__ __forceinline__ void rel_add1(unsigned* p) {
    asm volatile("red.release.gpu.add.u32 [%0], 1;" :: "l"(p) : "memory");
}
__device__ __forceinline__ unsigned acq_ld(const unsigned* p) {
    unsigned v;
    asm volatile("ld.acquire.gpu.u32 %0, [%1];" : "=r"(v) : "l"(p) : "memory");
    return v;
}

__global__ void rnn_init_kernel() {
    if (threadIdx.x < NGRP) g_cnt[threadIdx.x * 32] = 0u;
}

// 16-warp readout (w2 = 0..15): (b = w2&3, o0 = (w2>>2)*2), conflict-free 16B stride
__device__ __forceinline__ void do_readout(const float* hbuf, const float* who,
                                           int w2, int lane, int g, int cs,
                                           int srow, float* __restrict__ out) {
    const int b  = w2 & 3;
    const int o0 = (w2 >> 2) * 2;
    ull a0 = 0, a1 = 0;
#pragma unroll
    for (int c = 0; c < 4; c++) {
        int kk = c * 128 + lane * 4;
        ulonglong2 h2 = *(const ulonglong2*)&hbuf[b * H_ROW + kk];
        ulonglong2 w0 = *(const ulonglong2*)&who[o0 * WHO_ROW + kk];
        ulonglong2 w1 = *(const ulonglong2*)&who[(o0 + 1) * WHO_ROW + kk];
        a0 = fma2(h2.x, w0.x, a0); a0 = fma2(h2.y, w0.y, a0);
        a1 = fma2(h2.x, w1.x, a1); a1 = fma2(h2.y, w1.y, a1);
    }
    float f0 = lo2(a0) + hi2(a0);
    float f1 = lo2(a1) + hi2(a1);
#pragma unroll
    for (int off = 16; off; off >>= 1) {
        f0 += __shfl_xor_sync(~0u, f0, off);
        f1 += __shfl_xor_sync(~0u, f1, off);
    }
    if (lane == 0) {
        size_t base = ((size_t)(g * 4 + b) * S_LEN + srow) * OUT_D + cs * 8 + o0;
        out[base]     = f0;
        out[base + 1] = f1;
    }
}

__global__ void __launch_bounds__(NTHR, 1)
rnn_v12_kernel(const float* __restrict__ x,     // [64][2048][128]
               const float* __restrict__ Wih,   // [128][512]
               const float* __restrict__ Wrec,  // [512][512]
               const float* __restrict__ Who,   // [512][64]
               float* __restrict__ out)         // [64][2048][64]
{
    extern __shared__ float smem[];
    float* h_s   = smem + H_OFF;     // [2][4][520]
    float* x_s   = smem + X_OFF;     // [2][512]
    float* red   = smem + RED_OFF;   // [16][264]
    float* who_s = smem + WHO_OFF;   // [8][520]
    ull*   wih_s = (ull*)(smem + WIH_OFF);  // [16 ks][4 ip][64 nj]

    const int t    = threadIdx.x;
    const int warp = t >> 5, lane = t & 31;
    const int g    = blockIdx.x >> 3;      // batch group
    const int cs   = blockIdx.x & 7;       // column split

    // compute mapping: 64 cols (1 per thread-col-group), 16 k-splits of 32 k
    const int nj = t & 63;                 // column within slice
    const int ks = t >> 6;                 // k-split (uniform per warp-pair)
    const int n0 = cs * 64 + nj;
    const int k0 = ks * 32;
    const int i0 = ks * 8;
    unsigned* cnt = &g_cnt[g * 32];

    // ---- W_rec column slice -> registers, k-pair packed (16 ull) ----
    ull wr[16];
#pragma unroll
    for (int kp = 0; kp < 16; kp++)
        wr[kp] = pack2(Wrec[(k0 + 2 * kp) * HID + n0],
                       Wrec[(k0 + 2 * kp + 1) * HID + n0]);
    // ---- Wih slice -> packed smem (4 entries per thread) ----
#pragma unroll
    for (int ip = 0; ip < 4; ip++)
        wih_s[(ks * 4 + ip) * 64 + nj] = pack2(Wih[(i0 + 2 * ip) * HID + n0],
                                               Wih[(i0 + 2 * ip + 1) * HID + n0]);
    // Who o-slice transposed [o][k]
    for (int idx = t; idx < 8 * 512; idx += NTHR) {
        int ol = idx >> 9, k = idx & 511;
        who_s[ol * WHO_ROW + k] = Who[k * OUT_D + cs * 8 + ol];
    }
    // h0 = 0 in buffer 0; stage x[s=0] (threads 0-255)
    for (int idx = t; idx < H_BUF; idx += NTHR) h_s[idx] = 0.0f;
    if (t < 256) {
        int row = t >> 6, c2 = (t & 63) * 2;
        *(float2*)&x_s[row * 128 + c2] =
            *(const float2*)&x[((size_t)(g * 4 + row) * S_LEN) * IN_D + c2];
    }
    __syncthreads();

#pragma unroll 1
    for (int s = 0; s < S_LEN; s++) {
        const int ph = s & 1, pn = ph ^ 1;
        const float* hb = h_s + ph * H_BUF;
        const float* xb = x_s + ph * 512;

        // threads 0-255: prefetch next x early (hidden under GEMM)
        float2 xn = make_float2(0.0f, 0.0f);
        const int xrow = t >> 6, xc2 = (t & 63) * 2;
        if (t < 256 && s + 1 < S_LEN)
            xn = *(const float2*)&x[((size_t)(g * 4 + xrow) * S_LEN + (s + 1)) * IN_D + xc2];

        // ---- GEMM: h@Wrec + x@Wih ----
        ull acc[4];
#pragma unroll
        for (int q = 0; q < 4; q++) acc[q] = 0ull;
#pragma unroll
        for (int c = 0; c < 8; c++) {
            int kk = k0 + c * 4;
#pragma unroll
            for (int b = 0; b < 4; b++) {
                ulonglong2 h2 = *(const ulonglong2*)&hb[b * H_ROW + kk];  // warp-broadcast
                acc[b] = fma2(h2.x, wr[c * 2 + 0], acc[b]);
                acc[b] = fma2(h2.y, wr[c * 2 + 1], acc[b]);
            }
        }
#pragma unroll
        for (int ip = 0; ip < 4; ip++) {
            ull wv = wih_s[(ks * 4 + ip) * 64 + nj];
#pragma unroll
            for (int b = 0; b < 4; b++) {
                float2 xv = *(const float2*)&xb[b * 128 + i0 + 2 * ip];   // warp-broadcast
                acc[b] = fma2(pack2(xv.x, xv.y), wv, acc[b]);
            }
        }
        // partials -> red[ks][b*64 + nj]
#pragma unroll
        for (int b = 0; b < 4; b++)
            red[ks * RED_ROW + b * 64 + nj] = lo2(acc[b]) + hi2(acc[b]);
        __syncthreads();                          // S1

        if (t < 256) {
            // ---- finalize (critical path) ----
            const int ob = t >> 6, oc = t & 63;
            float pre = 0.0f;
#pragma unroll
            for (int r = 0; r < 16; r++) pre += red[r * RED_ROW + t];
            float hold = hb[ob * H_ROW + cs * 64 + oc];
            float hnew = (1.0f - ALPHA) * hold + ALPHA * my_tanh(pre);
            g_hbuf[pn][(size_t)(g * 4 + ob) * HID + cs * 64 + oc] = hnew;
            asm volatile("bar.sync 1, 256;" ::: "memory");   // finalize warps only
            if (t == 0) rel_add1(cnt);                       // release
            // x stage into next-parity buffer
            *(float2*)&x_s[pn * 512 + xrow * 128 + xc2] = xn;
        } else if (warp < 24) {
            // ---- shadowed readout of previous step (16 warps) ----
            if (s) do_readout(hb, who_s, warp - 8, lane, g, cs, s - 1, out);
        }

        // ---- poll + stage h_{s+1} (8B/thread), speculative fast path ----
        {
            const float* g_h = g_hbuf[pn];
            const int off = t * 2;
            float* hn = h_s + pn * H_BUF;
            unsigned target = 8u * (unsigned)(s + 1);
            bool ready = (acq_ld(cnt) >= target);
            float2 v = __ldcg((const float2*)&g_h[(size_t)g * 4 * HID + off]);  // speculative
            if (!ready) {
                while (acq_ld(cnt) < target) { }
                v = __ldcg((const float2*)&g_h[(size_t)g * 4 * HID + off]);     // reload
            }
            hn[(off >> 9) * H_ROW + (off & 511)]     = v.x;
            hn[(off >> 9) * H_ROW + (off & 511) + 1] = v.y;
        }
        __syncthreads();                          // S3: staged h + x visible to all
    }

    // epilogue: h_2048 staged into buffer 0 -> out row 2047
    if (warp >= 8 && warp < 24)
        do_readout(h_s, who_s, warp - 8, lane, g, cs, S_LEN - 1, out);
}

extern "C" void kernel_launch(void* const* d_in, const int* in_sizes, int n_in,
                              void* d_out, int out_size) {
    const float* x    = (const float*)d_in[0];
    const float* Wih  = (const float*)d_in[1];
    const float* Wrec = (const float*)d_in[2];
    const float* Who  = (const float*)d_in[3];
    float* out = (float*)d_out;

    rnn_init_kernel<<<1, 32>>>();
    cudaFuncSetAttribute(rnn_v12_kernel,
                         cudaFuncAttributeMaxDynamicSharedMemorySize, SMEM_BYTES);
    rnn_v12_kernel<<<NGRP * NCS, NTHR, SMEM_BYTES>>>(x, Wih, Wrec, Who, out);
}

// round 13
// speedup vs baseline: 1.2169x; 1.2169x over previous
#include <cuda_runtime.h>
#include <cuda_bf16.h>
#include <cstdint>

#define S_LEN 2048
#define HID   512
#define IN_D  128
#define OUT_D 64
#define ALPHA 0.2f
#define NCS   8          // column-split CTAs per batch group
#define NGRP  16         // batch groups
#define NTHR  512

typedef unsigned long long ull;

// ---- dynamic smem layout (float offsets) ----
// hstg: [2 buf][16 ks][4 b][36 (32 k + pad)] -> warp tile row = 144 floats
#define HSTG_ROWB 36
#define HSTG_WARP 144
#define HSTG_BUF  (16 * HSTG_WARP)          // 2304
#define HSTG_OFF  0                          // 2 * 2304 = 4608
#define XSTG_OFF  4608                       // [2][16][32] = 1024
#define RED_ROW   264
#define RED_OFF   5632                       // [16][264] = 4224
#define WHO_ROW   520
#define WHO_OFF   9856                       // [8][520] = 4160
#define WIH_OFF   14016                      // packed Wih: 4096 ull = 8192 floats
#define HLOC_OFF  22208                      // [2][256] = 512
#define SMEM_FLOATS 22720
#define SMEM_BYTES  (SMEM_FLOATS * 4)        // 90880

// L2-exchanged state
__device__ float    g_hbuf[2][64 * HID];
__device__ unsigned g_cnt[NGRP * 32];

// ---------------- packed f32x2 helpers ----------------
__device__ __forceinline__ ull fma2(ull a, ull b, ull c) {
    ull d;
    asm("fma.rn.f32x2 %0, %1, %2, %3;" : "=l"(d) : "l"(a), "l"(b), "l"(c));
    return d;
}
__device__ __forceinline__ ull pack2(float a, float b) {
    ull r;
    asm("mov.b64 %0, {%1, %2};" : "=l"(r) : "r"(__float_as_uint(a)), "r"(__float_as_uint(b)));
    return r;
}
__device__ __forceinline__ float lo2(ull v) { return __uint_as_float((unsigned)(v & 0xffffffffull)); }
__device__ __forceinline__ float hi2(ull v) { return __uint_as_float((unsigned)(v >> 32)); }
__device__ __forceinline__ float my_tanh(float v) {
    float e = __expf(2.0f * v);               // inf -> exactly +1, branch-free
    return 1.0f - __fdividef(2.0f, e + 1.0f);
}
__device__ __forceinline__ void rel_add1(unsigned* p) {
    asm volatile("red.release.gpu.add.u32 [%0], 1;" :: "l"(p) : "memory");
}
__device__ __forceinline__ unsigned acq_ld(const unsigned* p) {
    unsigned v;
    asm volatile("ld.acquire.gpu.u32 %0, [%1];" : "=r"(v) : "l"(p) : "memory");
    return v;
}

__global__ void rnn_init_kernel() {
    if (threadIdx.x < NGRP) g_cnt[threadIdx.x * 32] = 0u;
}

// 8-warp readout (w2 = 0..7): b = w2&3, o0 = (w2>>2)*4. Reads full h from the
// padded hstg buffer: k = c*128 + lane*4 -> ks = c*4 + (lane>>3), kk = (lane&7)*4.
// Conflict-free per 8-lane phase for both hstg and who_s.
__device__ __forceinline__ void do_readout8(const float* hbuf, const float* who,
                                            int w2, int lane, int g, int cs,
                                            int srow, float* __restrict__ out) {
    const int b  = w2 & 3;
    const int o0 = (w2 >> 2) * 4;
    const int hsub = (lane >> 3) * HSTG_WARP + b * HSTG_ROWB + (lane & 7) * 4;
    ull a0 = 0, a1 = 0, a2 = 0, a3 = 0;
#pragma unroll
    for (int c = 0; c < 4; c++) {
        int kk = c * 128 + lane * 4;
        ulonglong2 h2 = *(const ulonglong2*)&hbuf[c * 4 * HSTG_WARP + hsub];
        ulonglong2 w0 = *(const ulonglong2*)&who[(o0 + 0) * WHO_ROW + kk];
        ulonglong2 w1 = *(const ulonglong2*)&who[(o0 + 1) * WHO_ROW + kk];
        ulonglong2 w2v = *(const ulonglong2*)&who[(o0 + 2) * WHO_ROW + kk];
        ulonglong2 w3 = *(const ulonglong2*)&who[(o0 + 3) * WHO_ROW + kk];
        a0 = fma2(h2.x, w0.x, a0);  a0 = fma2(h2.y, w0.y, a0);
        a1 = fma2(h2.x, w1.x, a1);  a1 = fma2(h2.y, w1.y, a1);
        a2 = fma2(h2.x, w2v.x, a2); a2 = fma2(h2.y, w2v.y, a2);
        a3 = fma2(h2.x, w3.x, a3);  a3 = fma2(h2.y, w3.y, a3);
    }
    float f0 = lo2(a0) + hi2(a0);
    float f1 = lo2(a1) + hi2(a1);
    float f2 = lo2(a2) + hi2(a2);
    float f3 = lo2(a3) + hi2(a3);
#pragma unroll
    for (int off = 16; off; off >>= 1) {
        f0 += __shfl_xor_sync(~0u, f0, off);
        f1 += __shfl_xor_sync(~0u, f1, off);
        f2 += __shfl_xor_sync(~0u, f2, off);
        f3 += __shfl_xor_sync(~0u, f3, off);
    }
    if (lane == 0) {
        size_t base = ((size_t)(g * 4 + b) * S_LEN + srow) * OUT_D + cs * 8 + o0;
        *(float4*)&out[base] = make_float4(f0, f1, f2, f3);
    }
}

__global__ void __launch_bounds__(NTHR, 1)
rnn_v13_kernel(const float* __restrict__ x,     // [64][2048][128]
               const float* __restrict__ Wih,   // [128][512]
               const float* __restrict__ Wrec,  // [512][512]
               const float* __restrict__ Who,   // [512][64]
               float* __restrict__ out)         // [64][2048][64]
{
    extern __shared__ float smem[];
    float* hstg  = smem + HSTG_OFF;   // [2][16][4][36]
    float* xstg  = smem + XSTG_OFF;   // [2][16][32]
    float* red   = smem + RED_OFF;    // [16][264]
    float* who_s = smem + WHO_OFF;    // [8][520]
    ull*   wih_s = (ull*)(smem + WIH_OFF);  // [16 ks][4 ip][64]
    float* hloc  = smem + HLOC_OFF;   // [2][256]

    const int t    = threadIdx.x;
    const int warp = t >> 5, lane = t & 31;
    const int g    = blockIdx.x >> 3;      // batch group
    const int cs   = blockIdx.x & 7;       // column split

    // compute mapping: 32 n-groups of 2 cols, 16 k-splits of 32 k
    const int nj = t & 31;
    const int ks = warp;
    const int n0 = cs * 64 + nj * 2;
    const int k0 = ks * 32;
    const int i0 = ks * 8;
    unsigned* cnt = &g_cnt[g * 32];

    // stage-lane mapping (warp tile = [4 b][32 k], 16B per lane)
    const int sb = lane >> 3;              // b row
    const int sk = (lane & 7) * 4;         // k offset within 32
    const int si = lane & 7;               // i offset for x (b*8+i layout uses lane>>3 too)

    // ---- W_rec slice -> registers, k-pair packed ----
    ull wr[32];
#pragma unroll
    for (int kp = 0; kp < 16; kp++) {
        float2 we = *(const float2*)&Wrec[(k0 + 2 * kp)     * HID + n0];
        float2 wo = *(const float2*)&Wrec[(k0 + 2 * kp + 1) * HID + n0];
        wr[kp * 2 + 0] = pack2(we.x, wo.x);
        wr[kp * 2 + 1] = pack2(we.y, wo.y);
    }
    // ---- Wih slice -> packed smem ----
#pragma unroll
    for (int ip = 0; ip < 4; ip++) {
        float2 we = *(const float2*)&Wih[(i0 + 2 * ip)     * HID + n0];
        float2 wo = *(const float2*)&Wih[(i0 + 2 * ip + 1) * HID + n0];
        wih_s[(ks * 4 + ip) * 64 + nj * 2 + 0] = pack2(we.x, wo.x);
        wih_s[(ks * 4 + ip) * 64 + nj * 2 + 1] = pack2(we.y, wo.y);
    }
    // Who o-slice transposed [o][k]
    for (int idx = t; idx < 8 * 512; idx += NTHR) {
        int ol = idx >> 9, k = idx & 511;
        who_s[ol * WHO_ROW + k] = Who[k * OUT_D + cs * 8 + ol];
    }
    // hloc zero (both parities); hstg buffer0 zero (h0 = 0); xstg[0] load x[s=0]
    if (t < 512) hloc[t & 511] = 0.0f;
    {
        float* hw = hstg + 0 * HSTG_BUF + warp * HSTG_WARP;
        *(float4*)&hw[sb * HSTG_ROWB + sk] = make_float4(0.f, 0.f, 0.f, 0.f);
        xstg[0 * 512 + warp * 32 + lane] =
            x[((size_t)(g * 4 + sb) * S_LEN + 0) * IN_D + i0 + si];
    }
    __syncthreads();

#pragma unroll 1
    for (int s = 0; s < S_LEN; s++) {
        const int ph = s & 1, pn = ph ^ 1;
        const float* hb = hstg + ph * HSTG_BUF + warp * HSTG_WARP;   // own tile
        const float* xb = xstg + ph * 512 + warp * 32;

        // prefetch next x (1 float/lane, hidden under GEMM)
        float xn = 0.0f;
        if (s + 1 < S_LEN)
            xn = x[((size_t)(g * 4 + sb) * S_LEN + (s + 1)) * IN_D + i0 + si];

        // ---- GEMM: h@Wrec + x@Wih from warp-private tiles ----
        ull acc[8];
#pragma unroll
        for (int q = 0; q < 8; q++) acc[q] = 0ull;
#pragma unroll
        for (int c = 0; c < 8; c++) {
#pragma unroll
            for (int b = 0; b < 4; b++) {
                ulonglong2 h2 = *(const ulonglong2*)&hb[b * HSTG_ROWB + c * 4]; // broadcast
                acc[b * 2 + 0] = fma2(h2.x, wr[(c * 2) * 2 + 0],     acc[b * 2 + 0]);
                acc[b * 2 + 1] = fma2(h2.x, wr[(c * 2) * 2 + 1],     acc[b * 2 + 1]);
                acc[b * 2 + 0] = fma2(h2.y, wr[(c * 2 + 1) * 2 + 0], acc[b * 2 + 0]);
                acc[b * 2 + 1] = fma2(h2.y, wr[(c * 2 + 1) * 2 + 1], acc[b * 2 + 1]);
            }
        }
#pragma unroll
        for (int ip = 0; ip < 4; ip++) {
            ulonglong2 wv = *(const ulonglong2*)&wih_s[(ks * 4 + ip) * 64 + nj * 2];
#pragma unroll
            for (int b = 0; b < 4; b++) {
                float2 xv = *(const float2*)&xb[b * 8 + 2 * ip];                // broadcast
                ull xp = pack2(xv.x, xv.y);
                acc[b * 2 + 0] = fma2(xp, wv.x, acc[b * 2 + 0]);
                acc[b * 2 + 1] = fma2(xp, wv.y, acc[b * 2 + 1]);
            }
        }
#pragma unroll
        for (int b = 0; b < 4; b++) {
            float2 v;
            v.x = lo2(acc[b * 2 + 0]) + hi2(acc[b * 2 + 0]);
            v.y = lo2(acc[b * 2 + 1]) + hi2(acc[b * 2 + 1]);
            *(float2*)&red[ks * RED_ROW + b * 64 + nj * 2] = v;
        }
        // stage prefetched x into next-parity warp slot (ordered by stage syncwarp)
        xstg[pn * 512 + warp * 32 + lane] = xn;

        __syncthreads();                          // S1: red ready; also orders
                                                  // last iter's staging before readout

        if (t < 256) {
            // ---- finalize (critical path) ----
            const int ob = t >> 6, oc = t & 63;
            float pre = 0.0f;
#pragma unroll
            for (int r = 0; r < 16; r++) pre += red[r * RED_ROW + t];
            float hold = hloc[ph * 256 + t];
            float hnew = (1.0f - ALPHA) * hold + ALPHA * my_tanh(pre);
            g_hbuf[pn][(size_t)(g * 4 + ob) * HID + cs * 64 + oc] = hnew;
            hloc[pn * 256 + t] = hnew;
            asm volatile("bar.sync 1, 256;" ::: "memory");   // finalize warps only
            if (t == 0) rel_add1(cnt);                       // release
        } else if (s) {
            // ---- shadowed readout of row s-1 from hstg[ph] (full h) ----
            do_readout8(hstg + ph * HSTG_BUF, who_s, warp - 8, lane, g, cs, s - 1, out);
        }

        // ---- poll peers, then warp-self stage of own h_{s+1} tile ----
        {
            unsigned target = 8u * (unsigned)(s + 1);
            while (acq_ld(cnt) < target) { }
        }
        {
            float4 hv = __ldcg((const float4*)
                &g_hbuf[pn][(size_t)(g * 4 + sb) * HID + k0 + sk]);
            float* hw = hstg + pn * HSTG_BUF + warp * HSTG_WARP;
            *(float4*)&hw[sb * HSTG_ROWB + sk] = hv;
        }
        __syncwarp();                             // own tile + own x slot visible in-warp
    }

    // ---- epilogue: readout row 2047 from hstg[0] (h_2048, staged at s=2047) ----
    __syncthreads();
    if (warp >= 8)
        do_readout8(hstg + 0 * HSTG_BUF, who_s, warp - 8, lane, g, cs, S_LEN - 1, out);
}

extern "C" void kernel_launch(void* const* d_in, const int* in_sizes, int n_in,
                              void* d_out, int out_size) {
    const float* x    = (const float*)d_in[0];
    const float* Wih  = (const float*)d_in[1];
    const float* Wrec = (const float*)d_in[2];
    const float* Who  = (const float*)d_in[3];
    float* out = (float*)d_out;

    rnn_init_kernel<<<1, 32>>>();
    cudaFuncSetAttribute(rnn_v13_kernel,
                         cudaFuncAttributeMaxDynamicSharedMemorySize, SMEM_BYTES);
    rnn_v13_kernel<<<NGRP * NCS, NTHR, SMEM_BYTES>>>(x, Wih, Wrec, Who, out);
}

// round 14
// speedup vs baseline: 1.2610x; 1.0362x over previous
#include <cuda_runtime.h>
#include <cuda_bf16.h>
#include <cstdint>

#define S_LEN 2048
#define HID   512
#define IN_D  128
#define OUT_D 64
#define ALPHA 0.2f
#define NCS   8          // column-split CTAs per super-group
#define NSG   16         // super-groups (4 batch rows each; 2 chains of 2 rows)
#define NTHR  512

typedef unsigned long long ull;

// ---- dynamic smem layout (float offsets) ----
// hstg[grp][par][16 warps][2 b][36]   (72 per warp)
#define HSTG_BASE 0
#define HSTG(grp, par) (smem + HSTG_BASE + (grp) * 2304 + (par) * 1152)
#define XSTG_BASE 4608
#define XSTG(grp, par) (smem + XSTG_BASE + (grp) * 512 + (par) * 256)   // [16][16]
#define RED_BASE  5632
#define RED_ROW   132
#define REDB(grp) (smem + RED_BASE + (grp) * 2112)                      // [16][132]
#define WHO_BASE  9856                                                  // [8][520]
#define WHO_ROW   520
#define WIH_BASE  14016                                                 // 4096 ull
#define HLOC_BASE 22208
#define HLOC(grp, par) (smem + HLOC_BASE + (grp) * 256 + (par) * 128)   // [128]
#define SMEM_FLOATS 22720
#define SMEM_BYTES  (SMEM_FLOATS * 4)   // 90880

// L2-exchanged state: h rows 0..63, double-buffered by parity
__device__ float    g_hbuf[2][64 * HID];
__device__ unsigned g_cnt[32 * 32];     // counter per (super-group, chain), 128B apart

// ---------------- packed f32x2 helpers ----------------
__device__ __forceinline__ ull fma2(ull a, ull b, ull c) {
    ull d;
    asm("fma.rn.f32x2 %0, %1, %2, %3;" : "=l"(d) : "l"(a), "l"(b), "l"(c));
    return d;
}
__device__ __forceinline__ ull pack2(float a, float b) {
    ull r;
    asm("mov.b64 %0, {%1, %2};" : "=l"(r) : "r"(__float_as_uint(a)), "r"(__float_as_uint(b)));
    return r;
}
__device__ __forceinline__ float lo2(ull v) { return __uint_as_float((unsigned)(v & 0xffffffffull)); }
__device__ __forceinline__ float hi2(ull v) { return __uint_as_float((unsigned)(v >> 32)); }
__device__ __forceinline__ float my_tanh(float v) {
    float e = __expf(2.0f * v);               // inf -> exactly +1, branch-free
    return 1.0f - __fdividef(2.0f, e + 1.0f);
}
__device__ __forceinline__ void rel_add1(unsigned* p) {
    asm volatile("red.release.gpu.add.u32 [%0], 1;" :: "l"(p) : "memory");
}
__device__ __forceinline__ unsigned acq_ld(const unsigned* p) {
    unsigned v;
    asm volatile("ld.acquire.gpu.u32 %0, [%1];" : "=r"(v) : "l"(p) : "memory");
    return v;
}

__global__ void rnn_init_kernel() {     // <<<2, 512>>>
    int i = blockIdx.x * 512 + threadIdx.x;
    if (i < 32 * 32) g_cnt[i] = 0u;
}

// readout of one chain: 8 warps (w2=0..7): b = w2&1, o0 = (w2>>1)*2.
// hs = staged full-h of the chain (padded [16][2][36]); who = [8 o][520].
__device__ __forceinline__ void readout2(const float* hs, const float* who,
                                         int w2, int lane, int rowbase, int srow,
                                         int cs, float* __restrict__ out) {
    const int b  = w2 & 1;
    const int o0 = (w2 >> 1) * 2;
    ull a0 = 0, a1 = 0;
#pragma unroll
    for (int c = 0; c < 4; c++) {
        int ksi = c * 4 + (lane >> 3);
        int kk  = (lane & 7) * 4;
        int kg  = c * 128 + lane * 4;
        ulonglong2 h2 = *(const ulonglong2*)&hs[ksi * 72 + b * 36 + kk];
        ulonglong2 w0 = *(const ulonglong2*)&who[o0 * WHO_ROW + kg];
        ulonglong2 w1 = *(const ulonglong2*)&who[(o0 + 1) * WHO_ROW + kg];
        a0 = fma2(h2.x, w0.x, a0); a0 = fma2(h2.y, w0.y, a0);
        a1 = fma2(h2.x, w1.x, a1); a1 = fma2(h2.y, w1.y, a1);
    }
    float f0 = lo2(a0) + hi2(a0);
    float f1 = lo2(a1) + hi2(a1);
#pragma unroll
    for (int off = 16; off; off >>= 1) {
        f0 += __shfl_xor_sync(~0u, f0, off);
        f1 += __shfl_xor_sync(~0u, f1, off);
    }
    if (lane == 0) {
        size_t base = ((size_t)(rowbase + b) * S_LEN + srow) * OUT_D + cs * 8 + o0;
        *(float2*)&out[base] = make_float2(f0, f1);
    }
}

__global__ void __launch_bounds__(NTHR, 1)
rnn_v14_kernel(const float* __restrict__ x,     // [64][2048][128]
               const float* __restrict__ Wih,   // [128][512]
               const float* __restrict__ Wrec,  // [512][512]
               const float* __restrict__ Who,   // [512][64]
               float* __restrict__ out)         // [64][2048][64]
{
    extern __shared__ float smem[];
    float* who_s = smem + WHO_BASE;
    ull*   wih_s = (ull*)(smem + WIH_BASE);

    const int t    = threadIdx.x;
    const int warp = t >> 5, lane = t & 31;
    const int g4   = blockIdx.x >> 3;      // super-group (4 batch rows)
    const int cs   = blockIdx.x & 7;       // column split

    const int ks = warp;                   // 16 k-splits of 32
    const int n0 = cs * 64 + lane * 2;     // 2 cols/thread
    const int k0 = ks * 32;
    const int i0 = ks * 8;
    unsigned* cntA = &g_cnt[(g4 * 2 + 0) * 32];
    unsigned* cntB = &g_cnt[(g4 * 2 + 1) * 32];

    // stage-lane roles
    const int sb  = (lane >> 3) & 1, skk = (lane & 7) * 4;   // h stage (lane<16)
    const int xg  = lane >> 4, xb = (lane >> 3) & 1, xi = lane & 7;  // x prefetch
    const int xrow = g4 * 4 + xg * 2 + xb;

    // ---- W_rec slice -> registers, k-pair packed ----
    ull wr[32];
#pragma unroll
    for (int kp = 0; kp < 16; kp++) {
        float2 we = *(const float2*)&Wrec[(k0 + 2 * kp)     * HID + n0];
        float2 wo = *(const float2*)&Wrec[(k0 + 2 * kp + 1) * HID + n0];
        wr[kp * 2 + 0] = pack2(we.x, wo.x);
        wr[kp * 2 + 1] = pack2(we.y, wo.y);
    }
    // ---- Wih slice -> packed smem ----
#pragma unroll
    for (int ip = 0; ip < 4; ip++) {
        float2 we = *(const float2*)&Wih[(i0 + 2 * ip)     * HID + n0];
        float2 wo = *(const float2*)&Wih[(i0 + 2 * ip + 1) * HID + n0];
        wih_s[(ks * 4 + ip) * 64 + lane * 2 + 0] = pack2(we.x, wo.x);
        wih_s[(ks * 4 + ip) * 64 + lane * 2 + 1] = pack2(we.y, wo.y);
    }
    // Who o-slice transposed [o][k]
    for (int idx = t; idx < 8 * 512; idx += NTHR) {
        int ol = idx >> 9, k = idx & 511;
        who_s[ol * WHO_ROW + k] = Who[k * OUT_D + cs * 8 + ol];
    }
    // hloc zero; h0=0 staged (parity 0, both chains); x[0] staged
    if (t < 512) (smem + HLOC_BASE)[t] = 0.0f;
    if (lane < 16) {
        *(float4*)&HSTG(0, 0)[warp * 72 + sb * 36 + skk] = make_float4(0.f, 0.f, 0.f, 0.f);
        *(float4*)&HSTG(1, 0)[warp * 72 + sb * 36 + skk] = make_float4(0.f, 0.f, 0.f, 0.f);
    }
    XSTG(xg, 0)[warp * 16 + xb * 8 + xi] =
        x[((size_t)xrow * S_LEN + 0) * IN_D + i0 + xi];
    __syncthreads();

#pragma unroll 1
    for (int s = 0; s < S_LEN; s++) {
        const int ph = s & 1, pn = ph ^ 1;

        // prefetch x[s+1] for both chains (1 LDG/lane, retires under GEMMs)
        float xn = 0.0f;
        if (s + 1 < S_LEN)
            xn = x[((size_t)xrow * S_LEN + (s + 1)) * IN_D + i0 + xi];

        // ================= chain A: step s =================
        ull acc[4];
#pragma unroll
        for (int q = 0; q < 4; q++) acc[q] = 0ull;
        {
            const float* hb = HSTG(0, ph) + warp * 72;
            const float* xv = XSTG(0, ph) + warp * 16;
#pragma unroll
            for (int c = 0; c < 8; c++) {
#pragma unroll
                for (int b = 0; b < 2; b++) {
                    ulonglong2 h2 = *(const ulonglong2*)&hb[b * 36 + c * 4];  // broadcast
                    acc[b * 2 + 0] = fma2(h2.x, wr[(c * 2) * 2 + 0],     acc[b * 2 + 0]);
                    acc[b * 2 + 1] = fma2(h2.x, wr[(c * 2) * 2 + 1],     acc[b * 2 + 1]);
                    acc[b * 2 + 0] = fma2(h2.y, wr[(c * 2 + 1) * 2 + 0], acc[b * 2 + 0]);
                    acc[b * 2 + 1] = fma2(h2.y, wr[(c * 2 + 1) * 2 + 1], acc[b * 2 + 1]);
                }
            }
#pragma unroll
            for (int ip = 0; ip < 4; ip++) {
                ulonglong2 wv = *(const ulonglong2*)&wih_s[(ks * 4 + ip) * 64 + lane * 2];
#pragma unroll
                for (int b = 0; b < 2; b++) {
                    float2 xf = *(const float2*)&xv[b * 8 + 2 * ip];          // broadcast
                    ull xp = pack2(xf.x, xf.y);
                    acc[b * 2 + 0] = fma2(xp, wv.x, acc[b * 2 + 0]);
                    acc[b * 2 + 1] = fma2(xp, wv.y, acc[b * 2 + 1]);
                }
            }
#pragma unroll
            for (int b = 0; b < 2; b++)
                *(float2*)&REDB(0)[ks * RED_ROW + b * 64 + lane * 2] =
                    make_float2(lo2(acc[b * 2 + 0]) + hi2(acc[b * 2 + 0]),
                                lo2(acc[b * 2 + 1]) + hi2(acc[b * 2 + 1]));
        }
        // poll chain B state h_B[s] (released by peers at their iter s-1) + issue ldcg
        float4 hvB = make_float4(0.f, 0.f, 0.f, 0.f);
        if (s) {
            while (acq_ld(cntB) < 8u * (unsigned)s) { }
            if (lane < 16)
                hvB = __ldcg((const float4*)
                    &g_hbuf[ph][(size_t)(g4 * 4 + 2 + sb) * HID + k0 + skk]);
        }
        __syncthreads();                          // S1: red_A ready

        if (warp < 4) {
            // finalize A
            const int ob = t >> 6, oc = t & 63;
            float pre = 0.0f;
#pragma unroll
            for (int r = 0; r < 16; r++) pre += REDB(0)[r * RED_ROW + t];
            float hold = HLOC(0, ph)[t];
            float hnew = (1.0f - ALPHA) * hold + ALPHA * my_tanh(pre);
            g_hbuf[pn][(size_t)(g4 * 4 + ob) * HID + cs * 64 + oc] = hnew;
            HLOC(0, pn)[t] = hnew;
            asm volatile("bar.sync 1, 128;" ::: "memory");
            if (t == 0) rel_add1(cntA);
        } else if (warp < 12 && s) {
            readout2(HSTG(0, ph), who_s, warp - 4, lane, g4 * 4, s - 1, cs, out);
        }
        if (s && lane < 16)
            *(float4*)&HSTG(1, ph)[warp * 72 + sb * 36 + skk] = hvB;
        __syncwarp();

        // ================= chain B: step s =================
#pragma unroll
        for (int q = 0; q < 4; q++) acc[q] = 0ull;
        {
            const float* hb = HSTG(1, ph) + warp * 72;
            const float* xv = XSTG(1, ph) + warp * 16;
#pragma unroll
            for (int c = 0; c < 8; c++) {
#pragma unroll
                for (int b = 0; b < 2; b++) {
                    ulonglong2 h2 = *(const ulonglong2*)&hb[b * 36 + c * 4];
                    acc[b * 2 + 0] = fma2(h2.x, wr[(c * 2) * 2 + 0],     acc[b * 2 + 0]);
                    acc[b * 2 + 1] = fma2(h2.x, wr[(c * 2) * 2 + 1],     acc[b * 2 + 1]);
                    acc[b * 2 + 0] = fma2(h2.y, wr[(c * 2 + 1) * 2 + 0], acc[b * 2 + 0]);
                    acc[b * 2 + 1] = fma2(h2.y, wr[(c * 2 + 1) * 2 + 1], acc[b * 2 + 1]);
                }
            }
#pragma unroll
            for (int ip = 0; ip < 4; ip++) {
                ulonglong2 wv = *(const ulonglong2*)&wih_s[(ks * 4 + ip) * 64 + lane * 2];
#pragma unroll
                for (int b = 0; b < 2; b++) {
                    float2 xf = *(const float2*)&xv[b * 8 + 2 * ip];
                    ull xp = pack2(xf.x, xf.y);
                    acc[b * 2 + 0] = fma2(xp, wv.x, acc[b * 2 + 0]);
                    acc[b * 2 + 1] = fma2(xp, wv.y, acc[b * 2 + 1]);
                }
            }
#pragma unroll
            for (int b = 0; b < 2; b++)
                *(float2*)&REDB(1)[ks * RED_ROW + b * 64 + lane * 2] =
                    make_float2(lo2(acc[b * 2 + 0]) + hi2(acc[b * 2 + 0]),
                                lo2(acc[b * 2 + 1]) + hi2(acc[b * 2 + 1]));
        }
        // poll chain A state h_A[s+1] (includes our own release above) + issue ldcg
        float4 hvA;
        {
            while (acq_ld(cntA) < 8u * (unsigned)(s + 1)) { }
            if (lane < 16)
                hvA = __ldcg((const float4*)
                    &g_hbuf[pn][(size_t)(g4 * 4 + sb) * HID + k0 + skk]);
        }
        __syncthreads();                          // S2: red_B ready

        if (warp < 4) {
            // finalize B
            const int ob = t >> 6, oc = t & 63;
            float pre = 0.0f;
#pragma unroll
            for (int r = 0; r < 16; r++) pre += REDB(1)[r * RED_ROW + t];
            float hold = HLOC(1, ph)[t];
            float hnew = (1.0f - ALPHA) * hold + ALPHA * my_tanh(pre);
            g_hbuf[pn][(size_t)(g4 * 4 + 2 + ob) * HID + cs * 64 + oc] = hnew;
            HLOC(1, pn)[t] = hnew;
            asm volatile("bar.sync 1, 128;" ::: "memory");
            if (t == 0) rel_add1(cntB);
        } else if (warp < 12 && s) {
            readout2(HSTG(1, ph), who_s, warp - 4, lane, g4 * 4 + 2, s - 1, cs, out);
        }
        if (lane < 16)
            *(float4*)&HSTG(0, pn)[warp * 72 + sb * 36 + skk] = hvA;
        // stage x[s+1] for both chains into next parity
        XSTG(xg, pn)[warp * 16 + xb * 8 + xi] = xn;
        __syncwarp();
    }

    // ---- epilogue: rows 2047 for both chains (h[2048], parity 0) ----
    {
        while (acq_ld(cntB) < 8u * (unsigned)S_LEN) { }
        if (lane < 16) {
            float4 hv = __ldcg((const float4*)
                &g_hbuf[0][(size_t)(g4 * 4 + 2 + sb) * HID + k0 + skk]);
            *(float4*)&HSTG(1, 0)[warp * 72 + sb * 36 + skk] = hv;
        }
    }
    __syncthreads();
    if (warp >= 4 && warp < 12) {
        readout2(HSTG(0, 0), who_s, warp - 4, lane, g4 * 4,     S_LEN - 1, cs, out);
        readout2(HSTG(1, 0), who_s, warp - 4, lane, g4 * 4 + 2, S_LEN - 1, cs, out);
    }
}

extern "C" void kernel_launch(void* const* d_in, const int* in_sizes, int n_in,
                              void* d_out, int out_size) {
    const float* x    = (const float*)d_in[0];
    const float* Wih  = (const float*)d_in[1];
    const float* Wrec = (const float*)d_in[2];
    const float* Who  = (const float*)d_in[3];
    float* out = (float*)d_out;

    rnn_init_kernel<<<2, 512>>>();
    cudaFuncSetAttribute(rnn_v14_kernel,
                         cudaFuncAttributeMaxDynamicSharedMemorySize, SMEM_BYTES);
    rnn_v14_kernel<<<NSG * NCS, NTHR, SMEM_BYTES>>>(x, Wih, Wrec, Who, out);
}

// round 15
// speedup vs baseline: 1.2910x; 1.0238x over previous
#include <cuda_runtime.h>
#include <cuda_bf16.h>
#include <cstdint>

#define S_LEN 2048
#define HID   512
#define IN_D  128
#define OUT_D 64
#define ALPHA 0.2f
#define NCS   8          // column-split CTAs per batch group
#define NGRP  16         // batch groups
#define NTHR  512

typedef unsigned long long ull;

// ---- dynamic smem layout (float offsets) ----
#define H_ROW   520
#define H_BUF   (4 * H_ROW)                  // 2080
#define H_OFF   0                            // h[2][4][520]
#define X_OFF   (2 * H_BUF)                  // 4160 : x[2][512]
#define RED_ROW 264
#define RED_OFF (X_OFF + 2 * 512)            // 5184 : red[16][264]
#define WHO_ROW 520
#define WHO_OFF (RED_OFF + 16 * RED_ROW)     // 9408 : who[8][520]
#define WIH_OFF (WHO_OFF + 8 * WHO_ROW)      // 13568 : packed Wih, 4096 ull = 8192 floats
#define SMEM_FLOATS (WIH_OFF + 8192)         // 21760
#define SMEM_BYTES  (SMEM_FLOATS * 4)        // 87040

// L2-exchanged state
__device__ float    g_hbuf[2][64 * HID];
__device__ unsigned g_cnt[NGRP * 32];

// ---------------- packed f32x2 helpers ----------------
__device__ __forceinline__ ull fma2(ull a, ull b, ull c) {
    ull d;
    asm("fma.rn.f32x2 %0, %1, %2, %3;" : "=l"(d) : "l"(a), "l"(b), "l"(c));
    return d;
}
__device__ __forceinline__ ull pack2(float a, float b) {
    ull r;
    asm("mov.b64 %0, {%1, %2};" : "=l"(r) : "r"(__float_as_uint(a)), "r"(__float_as_uint(b)));
    return r;
}
__device__ __forceinline__ float lo2(ull v) { return __uint_as_float((unsigned)(v & 0xffffffffull)); }
__device__ __forceinline__ float hi2(ull v) { return __uint_as_float((unsigned)(v >> 32)); }
__device__ __forceinline__ float my_tanh(float v) {
    float e = __expf(2.0f * v);               // inf -> exactly +1, branch-free
    return 1.0f - __fdividef(2.0f, e + 1.0f);
}
__device__ __forceinline__ void rel_add1(unsigned* p) {
    asm volatile("red.release.gpu.add.u32 [%0], 1;" :: "l"(p) : "memory");
}
__device__ __forceinline__ unsigned acq_ld(const unsigned* p) {
    unsigned v;
    asm volatile("ld.acquire.gpu.u32 %0, [%1];" : "=r"(v) : "l"(p) : "memory");
    return v;
}

__global__ void rnn_init_kernel() {
    if (threadIdx.x < NGRP) g_cnt[threadIdx.x * 32] = 0u;
}

// 8-warp readout (w2 = 0..7): b = w2&3, o0 = (w2>>2)*4, conflict-free 16B stride
__device__ __forceinline__ void do_readout8(const float* hbuf, const float* who,
                                            int w2, int lane, int g, int cs,
                                            int srow, float* __restrict__ out) {
    const int b  = w2 & 3;
    const int o0 = (w2 >> 2) * 4;
    ull a0 = 0, a1 = 0, a2 = 0, a3 = 0;
#pragma unroll
    for (int c = 0; c < 4; c++) {
        int kk = c * 128 + lane * 4;
        ulonglong2 h2 = *(const ulonglong2*)&hbuf[b * H_ROW + kk];
        ulonglong2 w0 = *(const ulonglong2*)&who[(o0 + 0) * WHO_ROW + kk];
        ulonglong2 w1 = *(const ulonglong2*)&who[(o0 + 1) * WHO_ROW + kk];
        ulonglong2 w2v = *(const ulonglong2*)&who[(o0 + 2) * WHO_ROW + kk];
        ulonglong2 w3 = *(const ulonglong2*)&who[(o0 + 3) * WHO_ROW + kk];
        a0 = fma2(h2.x, w0.x, a0);  a0 = fma2(h2.y, w0.y, a0);
        a1 = fma2(h2.x, w1.x, a1);  a1 = fma2(h2.y, w1.y, a1);
        a2 = fma2(h2.x, w2v.x, a2); a2 = fma2(h2.y, w2v.y, a2);
        a3 = fma2(h2.x, w3.x, a3);  a3 = fma2(h2.y, w3.y, a3);
    }
    float f0 = lo2(a0) + hi2(a0);
    float f1 = lo2(a1) + hi2(a1);
    float f2 = lo2(a2) + hi2(a2);
    float f3 = lo2(a3) + hi2(a3);
#pragma unroll
    for (int off = 16; off; off >>= 1) {
        f0 += __shfl_xor_sync(~0u, f0, off);
        f1 += __shfl_xor_sync(~0u, f1, off);
        f2 += __shfl_xor_sync(~0u, f2, off);
        f3 += __shfl_xor_sync(~0u, f3, off);
    }
    if (lane == 0) {
        size_t base = ((size_t)(g * 4 + b) * S_LEN + srow) * OUT_D + cs * 8 + o0;
        *(float4*)&out[base] = make_float4(f0, f1, f2, f3);
    }
}

__global__ void __launch_bounds__(NTHR, 1)
rnn_v15_kernel(const float* __restrict__ x,     // [64][2048][128]
               const float* __restrict__ Wih,   // [128][512]
               const float* __restrict__ Wrec,  // [512][512]
               const float* __restrict__ Who,   // [512][64]
               float* __restrict__ out)         // [64][2048][64]
{
    extern __shared__ float smem[];
    float* h_s   = smem + H_OFF;     // [2][4][520]
    float* x_s   = smem + X_OFF;     // [2][512]
    float* red   = smem + RED_OFF;   // [16][264]
    float* who_s = smem + WHO_OFF;   // [8][520]
    ull*   wih_s = (ull*)(smem + WIH_OFF);  // [16 ks][4 ip][64]

    const int t    = threadIdx.x;
    const int warp = t >> 5, lane = t & 31;
    const int g    = blockIdx.x >> 3;      // batch group
    const int cs   = blockIdx.x & 7;       // column split

    // compute mapping: 32 n-groups of 2 cols, 16 k-splits of 32 k
    const int nj = t & 31;
    const int ks = warp;
    const int n0 = cs * 64 + nj * 2;
    const int k0 = ks * 32;
    const int i0 = ks * 8;
    unsigned* cnt = &g_cnt[g * 32];

    // shadow-warp (t>=256) staging mapping
    const int t2   = t & 255;
    const int xrow = t2 >> 6, xc2 = (t2 & 63) * 2;   // x tile: 8B/thread
    const int hoff = t2 * 8;                          // h tile: 32B/thread

    // ---- W_rec slice -> registers, k-pair packed ----
    ull wr[32];
#pragma unroll
    for (int kp = 0; kp < 16; kp++) {
        float2 we = *(const float2*)&Wrec[(k0 + 2 * kp)     * HID + n0];
        float2 wo = *(const float2*)&Wrec[(k0 + 2 * kp + 1) * HID + n0];
        wr[kp * 2 + 0] = pack2(we.x, wo.x);
        wr[kp * 2 + 1] = pack2(we.y, wo.y);
    }
    // ---- Wih slice -> packed smem ----
#pragma unroll
    for (int ip = 0; ip < 4; ip++) {
        float2 we = *(const float2*)&Wih[(i0 + 2 * ip)     * HID + n0];
        float2 wo = *(const float2*)&Wih[(i0 + 2 * ip + 1) * HID + n0];
        wih_s[(ks * 4 + ip) * 64 + nj * 2 + 0] = pack2(we.x, wo.x);
        wih_s[(ks * 4 + ip) * 64 + nj * 2 + 1] = pack2(we.y, wo.y);
    }
    // Who o-slice transposed [o][k]
    for (int idx = t; idx < 8 * 512; idx += NTHR) {
        int ol = idx >> 9, k = idx & 511;
        who_s[ol * WHO_ROW + k] = Who[k * OUT_D + cs * 8 + ol];
    }
    // h0 = 0 in buffer 0; stage x[s=0]
    for (int idx = t; idx < H_BUF; idx += NTHR) h_s[idx] = 0.0f;
    if (t >= 256)
        *(float2*)&x_s[xrow * 128 + xc2] =
            *(const float2*)&x[((size_t)(g * 4 + xrow) * S_LEN) * IN_D + xc2];
    __syncthreads();

#pragma unroll 1
    for (int s = 0; s < S_LEN; s++) {
        const int ph = s & 1, pn = ph ^ 1;
        const float* hb = h_s + ph * H_BUF;
        const float* xb = x_s + ph * 512;

        // ---- GEMM: h@Wrec + x@Wih (all 16 warps) ----
        ull acc[8];
#pragma unroll
        for (int q = 0; q < 8; q++) acc[q] = 0ull;
#pragma unroll
        for (int c = 0; c < 8; c++) {
            int kk = k0 + c * 4;
#pragma unroll
            for (int b = 0; b < 4; b++) {
                ulonglong2 h2 = *(const ulonglong2*)&hb[b * H_ROW + kk];  // broadcast
                acc[b * 2 + 0] = fma2(h2.x, wr[(c * 2) * 2 + 0],     acc[b * 2 + 0]);
                acc[b * 2 + 1] = fma2(h2.x, wr[(c * 2) * 2 + 1],     acc[b * 2 + 1]);
                acc[b * 2 + 0] = fma2(h2.y, wr[(c * 2 + 1) * 2 + 0], acc[b * 2 + 0]);
                acc[b * 2 + 1] = fma2(h2.y, wr[(c * 2 + 1) * 2 + 1], acc[b * 2 + 1]);
            }
        }
#pragma unroll
        for (int ip = 0; ip < 4; ip++) {
            ulonglong2 wv = *(const ulonglong2*)&wih_s[(ks * 4 + ip) * 64 + nj * 2];
#pragma unroll
            for (int b = 0; b < 4; b++) {
                float2 xv = *(const float2*)&xb[b * 128 + i0 + 2 * ip];   // broadcast
                ull xp = pack2(xv.x, xv.y);
                acc[b * 2 + 0] = fma2(xp, wv.x, acc[b * 2 + 0]);
                acc[b * 2 + 1] = fma2(xp, wv.y, acc[b * 2 + 1]);
            }
        }
#pragma unroll
        for (int b = 0; b < 4; b++) {
            float2 v;
            v.x = lo2(acc[b * 2 + 0]) + hi2(acc[b * 2 + 0]);
            v.y = lo2(acc[b * 2 + 1]) + hi2(acc[b * 2 + 1]);
            *(float2*)&red[ks * RED_ROW + b * 64 + nj * 2] = v;
        }
        __syncthreads();                          // S1: partials visible

        if (t < 256) {
            // ======== critical path: finalize, then shadowed readout ========
            const int ob = t >> 6, oc = t & 63;
            float pre = 0.0f;
#pragma unroll
            for (int r = 0; r < 16; r++) pre += red[r * RED_ROW + t];
            float hold = hb[ob * H_ROW + cs * 64 + oc];
            float hnew = (1.0f - ALPHA) * hold + ALPHA * my_tanh(pre);
            g_hbuf[pn][(size_t)(g * 4 + ob) * HID + cs * 64 + oc] = hnew;
            asm volatile("bar.sync 1, 256;" ::: "memory");   // finalize warps only
            if (t == 0) rel_add1(cnt);                       // release

            // readout of row s-1 shadows release propagation + peers' polls
            if (s) do_readout8(hb, who_s, warp, lane, g, cs, s - 1, out);
        } else {
            // ======== shadow path: x prefetch, poll, stage h_{s+1} + x ========
            float2 xn = make_float2(0.0f, 0.0f);
            if (s + 1 < S_LEN)
                xn = *(const float2*)&x[((size_t)(g * 4 + xrow) * S_LEN + (s + 1)) * IN_D + xc2];

            unsigned target = 8u * (unsigned)(s + 1);
            while (acq_ld(cnt) < target) { }

            const float* g_h = g_hbuf[pn];
            float4 a  = __ldcg((const float4*)&g_h[(size_t)g * 4 * HID + hoff]);
            float4 b4 = __ldcg((const float4*)&g_h[(size_t)g * 4 * HID + hoff + 4]);
            float* hn = h_s + pn * H_BUF;
            int bb2 = hoff >> 9, kk2 = hoff & 511;
            *(float4*)&hn[bb2 * H_ROW + kk2]     = a;
            *(float4*)&hn[bb2 * H_ROW + kk2 + 4] = b4;
            *(float2*)&x_s[pn * 512 + xrow * 128 + xc2] = xn;
        }
        __syncthreads();                          // S3: staged h + x visible to all
    }

    // epilogue: h_2048 staged into buffer 0 at s=2047 -> out row 2047
    if (t < 256)
        do_readout8(h_s, who_s, warp, lane, g, cs, S_LEN - 1, out);
}

extern "C" void kernel_launch(void* const* d_in, const int* in_sizes, int n_in,
                              void* d_out, int out_size) {
    const float* x    = (const float*)d_in[0];
    const float* Wih  = (const float*)d_in[1];
    const float* Wrec = (const float*)d_in[2];
    const float* Who  = (const float*)d_in[3];
    float* out = (float*)d_out;

    rnn_init_kernel<<<1, 32>>>();
    cudaFuncSetAttribute(rnn_v15_kernel,
                         cudaFuncAttributeMaxDynamicSharedMemorySize, SMEM_BYTES);
    rnn_v15_kernel<<<NGRP * NCS, NTHR, SMEM_BYTES>>>(x, Wih, Wrec, Who, out);
}

// round 16
// speedup vs baseline: 1.2925x; 1.0012x over previous
#include <cuda_runtime.h>
#include <cuda_bf16.h>
#include <cstdint>

#define S_LEN 2048
#define HID   512
#define IN_D  128
#define OUT_D 64
#define ALPHA 0.2f
#define NCS   8          // column-split CTAs per batch group
#define NGRP  16         // batch groups
#define NTHR  512
#define CANARY 0x7F800001u   // sNaN bit pattern; tanh/leaky output can never equal it

typedef unsigned long long ull;

// ---- dynamic smem layout (float offsets) ----
#define H_ROW   520
#define H_BUF   (4 * H_ROW)                  // 2080
#define H_OFF   0                            // h[2][4][520]
#define X_OFF   (2 * H_BUF)                  // 4160 : x[2][512]
#define RED_ROW 264
#define RED_OFF (X_OFF + 2 * 512)            // 5184 : red[16][264]
#define WHO_ROW 520
#define WHO_OFF (RED_OFF + 16 * RED_ROW)     // 9408 : who[8][520]
#define WIH_OFF (WHO_OFF + 8 * WHO_ROW)      // 13568 : packed Wih, 4096 ull = 8192 floats
#define SMEM_FLOATS (WIH_OFF + 8192)         // 21760
#define SMEM_BYTES  (SMEM_FLOATS * 4)        // 87040

// depth-3 self-tagged h exchange ring
__device__ float g_ring[3][64 * HID];

// ---------------- packed f32x2 helpers ----------------
__device__ __forceinline__ ull fma2(ull a, ull b, ull c) {
    ull d;
    asm("fma.rn.f32x2 %0, %1, %2, %3;" : "=l"(d) : "l"(a), "l"(b), "l"(c));
    return d;
}
__device__ __forceinline__ ull pack2(float a, float b) {
    ull r;
    asm("mov.b64 %0, {%1, %2};" : "=l"(r) : "r"(__float_as_uint(a)), "r"(__float_as_uint(b)));
    return r;
}
__device__ __forceinline__ float lo2(ull v) { return __uint_as_float((unsigned)(v & 0xffffffffull)); }
__device__ __forceinline__ float hi2(ull v) { return __uint_as_float((unsigned)(v >> 32)); }
__device__ __forceinline__ float my_tanh(float v) {
    float e = __expf(2.0f * v);               // inf -> exactly +1, branch-free
    return 1.0f - __fdividef(2.0f, e + 1.0f);
}
__device__ __forceinline__ uint4 ld_acq_v4(const unsigned* p) {
    uint4 v;
    asm volatile("ld.acquire.gpu.global.v4.u32 {%0,%1,%2,%3}, [%4];"
                 : "=r"(v.x), "=r"(v.y), "=r"(v.z), "=r"(v.w) : "l"(p) : "memory");
    return v;
}
__device__ __forceinline__ void st_rel_f32(float* p, float v) {
    asm volatile("st.release.gpu.global.f32 [%0], %1;" :: "l"(p), "f"(v) : "memory");
}

__global__ void rnn_init_kernel() {   // <<<192, 512>>> : poison all 3 ring slots
    int i = blockIdx.x * 512 + threadIdx.x;     // 192*512 = 98304 = 3*64*512 exactly
    ((unsigned*)g_ring)[i] = CANARY;
}

// 16-warp readout: warp w -> (b = w&3, o0 = (w>>2)*2), conflict-free 16B stride
__device__ __forceinline__ void do_readout(const float* hbuf, const float* who,
                                           int w, int lane, int g, int cs,
                                           int srow, float* __restrict__ out) {
    const int b  = w & 3;
    const int o0 = (w >> 2) * 2;
    ull a0 = 0, a1 = 0;
#pragma unroll
    for (int c = 0; c < 4; c++) {
        int kk = c * 128 + lane * 4;                   // 16B lane stride
        ulonglong2 h2 = *(const ulonglong2*)&hbuf[b * H_ROW + kk];
        ulonglong2 w0 = *(const ulonglong2*)&who[o0 * WHO_ROW + kk];
        ulonglong2 w1 = *(const ulonglong2*)&who[(o0 + 1) * WHO_ROW + kk];
        a0 = fma2(h2.x, w0.x, a0); a0 = fma2(h2.y, w0.y, a0);
        a1 = fma2(h2.x, w1.x, a1); a1 = fma2(h2.y, w1.y, a1);
    }
    float f0 = lo2(a0) + hi2(a0);
    float f1 = lo2(a1) + hi2(a1);
#pragma unroll
    for (int off = 16; off; off >>= 1) {
        f0 += __shfl_xor_sync(~0u, f0, off);
        f1 += __shfl_xor_sync(~0u, f1, off);
    }
    if (lane == 0) {
        size_t base = ((size_t)(g * 4 + b) * S_LEN + srow) * OUT_D + cs * 8 + o0;
        out[base]     = f0;
        out[base + 1] = f1;
    }
}

__global__ void __launch_bounds__(NTHR, 1)
rnn_v16_kernel(const float* __restrict__ x,     // [64][2048][128]
               const float* __restrict__ Wih,   // [128][512]
               const float* __restrict__ Wrec,  // [512][512]
               const float* __restrict__ Who,   // [512][64]
               float* __restrict__ out)         // [64][2048][64]
{
    extern __shared__ float smem[];
    float* h_s   = smem + H_OFF;     // [2][4][520]
    float* x_s   = smem + X_OFF;     // [2][512]
    float* red   = smem + RED_OFF;   // [16][264]
    float* who_s = smem + WHO_OFF;   // [8][520]
    ull*   wih_s = (ull*)(smem + WIH_OFF);  // [16 ks][4 ip][64]

    const int t    = threadIdx.x;
    const int warp = t >> 5, lane = t & 31;
    const int g    = blockIdx.x >> 3;      // batch group
    const int cs   = blockIdx.x & 7;       // column split

    // compute mapping: 32 n-groups of 2 cols, 16 k-splits of 32 k
    const int nj = t & 31;
    const int ks = warp;
    const int n0 = cs * 64 + nj * 2;
    const int k0 = ks * 32;
    const int i0 = ks * 8;

    // ---- W_rec slice -> registers, k-pair packed ----
    ull wr[32];
#pragma unroll
    for (int kp = 0; kp < 16; kp++) {
        float2 we = *(const float2*)&Wrec[(k0 + 2 * kp)     * HID + n0];
        float2 wo = *(const float2*)&Wrec[(k0 + 2 * kp + 1) * HID + n0];
        wr[kp * 2 + 0] = pack2(we.x, wo.x);
        wr[kp * 2 + 1] = pack2(we.y, wo.y);
    }
    // ---- Wih slice -> packed smem ----
#pragma unroll
    for (int ip = 0; ip < 4; ip++) {
        float2 we = *(const float2*)&Wih[(i0 + 2 * ip)     * HID + n0];
        float2 wo = *(const float2*)&Wih[(i0 + 2 * ip + 1) * HID + n0];
        wih_s[(ks * 4 + ip) * 64 + nj * 2 + 0] = pack2(we.x, wo.x);
        wih_s[(ks * 4 + ip) * 64 + nj * 2 + 1] = pack2(we.y, wo.y);
    }
    // Who o-slice transposed [o][k]
    for (int idx = t; idx < 8 * 512; idx += NTHR) {
        int ol = idx >> 9, k = idx & 511;
        who_s[ol * WHO_ROW + k] = Who[k * OUT_D + cs * 8 + ol];
    }
    // h0 = 0 in buffer 0; stage x[s=0]
    for (int idx = t; idx < H_BUF; idx += NTHR) h_s[idx] = 0.0f;
    {
        int row = t >> 7, col = t & 127;
        x_s[row * 128 + col] = x[((size_t)(g * 4 + row) * S_LEN) * IN_D + col];
    }
    __syncthreads();

    int sl1 = 1, sl2 = 2;                    // (s+1)%3, (s+2)%3 running

#pragma unroll 1
    for (int s = 0; s < S_LEN; s++) {
        const int ph = s & 1, pn = ph ^ 1;
        const float* hb = h_s + ph * H_BUF;
        const float* xb = x_s + ph * 512;

        // prefetch next x early (consumed next step; STS after finalize)
        float xn = 0.0f;
        const int xrow = t >> 7, xcol = t & 127;
        if (s + 1 < S_LEN)
            xn = x[((size_t)(g * 4 + xrow) * S_LEN + (s + 1)) * IN_D + xcol];

        // ---- pre-activation partials: h@Wrec + x@Wih ----
        ull acc[8];
#pragma unroll
        for (int q = 0; q < 8; q++) acc[q] = 0ull;
#pragma unroll
        for (int c = 0; c < 8; c++) {
            int kk = k0 + c * 4;
#pragma unroll
            for (int b = 0; b < 4; b++) {
                ulonglong2 h2 = *(const ulonglong2*)&hb[b * H_ROW + kk];  // broadcast
                acc[b * 2 + 0] = fma2(h2.x, wr[(c * 2) * 2 + 0],     acc[b * 2 + 0]);
                acc[b * 2 + 1] = fma2(h2.x, wr[(c * 2) * 2 + 1],     acc[b * 2 + 1]);
                acc[b * 2 + 0] = fma2(h2.y, wr[(c * 2 + 1) * 2 + 0], acc[b * 2 + 0]);
                acc[b * 2 + 1] = fma2(h2.y, wr[(c * 2 + 1) * 2 + 1], acc[b * 2 + 1]);
            }
        }
#pragma unroll
        for (int ip = 0; ip < 4; ip++) {
            ulonglong2 wv = *(const ulonglong2*)&wih_s[(ks * 4 + ip) * 64 + nj * 2];
#pragma unroll
            for (int b = 0; b < 4; b++) {
                float2 xv = *(const float2*)&xb[b * 128 + i0 + 2 * ip];   // broadcast
                ull xp = pack2(xv.x, xv.y);
                acc[b * 2 + 0] = fma2(xp, wv.x, acc[b * 2 + 0]);
                acc[b * 2 + 1] = fma2(xp, wv.y, acc[b * 2 + 1]);
            }
        }
#pragma unroll
        for (int b = 0; b < 4; b++) {
            float2 v;
            v.x = lo2(acc[b * 2 + 0]) + hi2(acc[b * 2 + 0]);
            v.y = lo2(acc[b * 2 + 1]) + hi2(acc[b * 2 + 1]);
            *(float2*)&red[ks * RED_ROW + b * 64 + nj * 2] = v;
        }
        __syncthreads();                      // S1

        if (t < 256) {
            const int ob = t >> 6, oc = t & 63;
            const size_t widx = (size_t)(g * 4 + ob) * HID + cs * 64 + oc;
            // poison own word of the h_{s+2} slot (weak; ordered by the release below)
            ((unsigned*)g_ring[sl2])[widx] = CANARY;
            // reduce 16 k-splits
            float pre = 0.0f;
#pragma unroll
            for (int r = 0; r < 16; r++) pre += red[r * RED_ROW + t];
            float hold = hb[ob * H_ROW + cs * 64 + oc];
            float hnew = (1.0f - ALPHA) * hold + ALPHA * my_tanh(pre);
            // publish h_{s+1}: release store = the tag itself
            st_rel_f32(&g_ring[sl1][widx], hnew);
        }

        // ======== overlap window (h-independent) ========
        x_s[pn * 512 + xrow * 128 + xcol] = xn;
        if (s) do_readout(hb, who_s, warp, lane, g, cs, s - 1, out);

        // ---- self-tagged poll + stage h_{s+1} (16B/thread, one RTT) ----
        {
            const unsigned* src = (const unsigned*)g_ring[sl1] + (size_t)g * 4 * HID + t * 4;
            uint4 v;
            do {
                v = ld_acq_v4(src);
            } while (v.x == CANARY || v.y == CANARY || v.z == CANARY || v.w == CANARY);
            float* hn = h_s + pn * H_BUF;
            *(float4*)&hn[(t >> 7) * H_ROW + ((t * 4) & 511)] =
                make_float4(__uint_as_float(v.x), __uint_as_float(v.y),
                            __uint_as_float(v.z), __uint_as_float(v.w));
        }
        __syncthreads();                      // S3: staged h + x visible to all

        // advance ring indices: sl1 = (s+2)%3, sl2 = (s+3)%3
        sl1 = sl2;
        sl2 = sl2 + 1 - (sl2 == 2 ? 3 : 0);
    }

    // epilogue: h_2048 staged into buffer 0 at s=2047 -> out row 2047
    do_readout(h_s, who_s, warp, lane, g, cs, S_LEN - 1, out);
}

extern "C" void kernel_launch(void* const* d_in, const int* in_sizes, int n_in,
                              void* d_out, int out_size) {
    const float* x    = (const float*)d_in[0];
    const float* Wih  = (const float*)d_in[1];
    const float* Wrec = (const float*)d_in[2];
    const float* Who  = (const float*)d_in[3];
    float* out = (float*)d_out;

    rnn_init_kernel<<<192, 512>>>();
    cudaFuncSetAttribute(rnn_v16_kernel,
                         cudaFuncAttributeMaxDynamicSharedMemorySize, SMEM_BYTES);
    rnn_v16_kernel<<<NGRP * NCS, NTHR, SMEM_BYTES>>>(x, Wih, Wrec, Who, out);
}

// round 17
// speedup vs baseline: 1.4435x; 1.1168x over previous
#include <cuda_runtime.h>
#include <cuda_bf16.h>
#include <cstdint>

#define S_LEN 2048
#define HID   512
#define IN_D  128
#define OUT_D 64
#define ALPHA 0.2f
#define NCS   8          // column-split CTAs per batch group
#define NGRP  16         // batch groups
#define NTHR  512

typedef unsigned long long ull;

// ---- dynamic smem layout (float offsets) ----
#define H_ROW   520
#define H_BUF   (4 * H_ROW)                  // 2080
#define H_OFF   0                            // h[2][4][520]
#define X_OFF   (2 * H_BUF)                  // 4160 : x[2][512]
#define RED_ROW 264
#define RED_OFF (X_OFF + 2 * 512)            // 5184 : red[16][264]
#define WHO_ROW 520
#define WHO_OFF (RED_OFF + 16 * RED_ROW)     // 9408 : who[8][520]
#define WIH_OFF (WHO_OFF + 8 * WHO_ROW)      // 13568 : packed Wih, 4096 ull = 8192 floats
#define SMEM_FLOATS (WIH_OFF + 8192)         // 21760
#define SMEM_BYTES  (SMEM_FLOATS * 4)        // 87040

// L2-exchanged state
__device__ float    g_hbuf[2][64 * HID];
__device__ unsigned g_cnt[NGRP * 32];

// ---------------- packed f32x2 helpers ----------------
__device__ __forceinline__ ull fma2(ull a, ull b, ull c) {
    ull d;
    asm("fma.rn.f32x2 %0, %1, %2, %3;" : "=l"(d) : "l"(a), "l"(b), "l"(c));
    return d;
}
__device__ __forceinline__ ull pack2(float a, float b) {
    ull r;
    asm("mov.b64 %0, {%1, %2};" : "=l"(r) : "r"(__float_as_uint(a)), "r"(__float_as_uint(b)));
    return r;
}
__device__ __forceinline__ float lo2(ull v) { return __uint_as_float((unsigned)(v & 0xffffffffull)); }
__device__ __forceinline__ float hi2(ull v) { return __uint_as_float((unsigned)(v >> 32)); }
__device__ __forceinline__ float my_tanh(float v) {
    float e = __expf(2.0f * v);               // inf -> exactly +1, branch-free
    return 1.0f - __fdividef(2.0f, e + 1.0f);
}
__device__ __forceinline__ void rel_add1(unsigned* p) {
    asm volatile("red.release.gpu.add.u32 [%0], 1;" :: "l"(p) : "memory");
}
__device__ __forceinline__ unsigned acq_ld(const unsigned* p) {
    unsigned v;
    asm volatile("ld.acquire.gpu.u32 %0, [%1];" : "=r"(v) : "l"(p) : "memory");
    return v;
}

__global__ void rnn_init_kernel() {
    if (threadIdx.x < NGRP) g_cnt[threadIdx.x * 32] = 0u;
}

// 16-warp readout: warp w -> (b = w&3, o0 = (w>>2)*2), conflict-free 16B stride
__device__ __forceinline__ void do_readout(const float* hbuf, const float* who,
                                           int w, int lane, int g, int cs,
                                           int srow, float* __restrict__ out) {
    const int b  = w & 3;
    const int o0 = (w >> 2) * 2;
    ull a0 = 0, a1 = 0;
#pragma unroll
    for (int c = 0; c < 4; c++) {
        int kk = c * 128 + lane * 4;                   // 16B lane stride
        ulonglong2 h2 = *(const ulonglong2*)&hbuf[b * H_ROW + kk];
        ulonglong2 w0 = *(const ulonglong2*)&who[o0 * WHO_ROW + kk];
        ulonglong2 w1 = *(const ulonglong2*)&who[(o0 + 1) * WHO_ROW + kk];
        a0 = fma2(h2.x, w0.x, a0); a0 = fma2(h2.y, w0.y, a0);
        a1 = fma2(h2.x, w1.x, a1); a1 = fma2(h2.y, w1.y, a1);
    }
    float f0 = lo2(a0) + hi2(a0);
    float f1 = lo2(a1) + hi2(a1);
#pragma unroll
    for (int off = 16; off; off >>= 1) {
        f0 += __shfl_xor_sync(~0u, f0, off);
        f1 += __shfl_xor_sync(~0u, f1, off);
    }
    if (lane == 0) {
        size_t base = ((size_t)(g * 4 + b) * S_LEN + srow) * OUT_D + cs * 8 + o0;
        out[base]     = f0;
        out[base + 1] = f1;
    }
}

__global__ void __launch_bounds__(NTHR, 1)
rnn_v17_kernel(const float* __restrict__ x,     // [64][2048][128]
               const float* __restrict__ Wih,   // [128][512]
               const float* __restrict__ Wrec,  // [512][512]
               const float* __restrict__ Who,   // [512][64]
               float* __restrict__ out)         // [64][2048][64]
{
    extern __shared__ float smem[];
    float* h_s   = smem + H_OFF;     // [2][4][520]
    float* x_s   = smem + X_OFF;     // [2][512]
    float* red   = smem + RED_OFF;   // [16][264]
    float* who_s = smem + WHO_OFF;   // [8][520]
    ull*   wih_s = (ull*)(smem + WIH_OFF);  // [16 ks][4 ip][64]

    const int t    = threadIdx.x;
    const int warp = t >> 5, lane = t & 31;
    const int g    = blockIdx.x >> 3;      // batch group
    const int cs   = blockIdx.x & 7;       // column split

    // compute mapping: 32 n-groups of 2 cols, 16 k-splits of 32 k
    const int nj = t & 31;
    const int ks = t >> 5;                 // == warp
    const int n0 = cs * 64 + nj * 2;
    const int k0 = ks * 32;
    const int i0 = ks * 8;
    unsigned* cnt = &g_cnt[g * 32];

    // ---- W_rec slice -> registers, k-pair packed: wr[16 kp][2 j] ----
    ull wr[32];
#pragma unroll
    for (int kp = 0; kp < 16; kp++) {
        float2 we = *(const float2*)&Wrec[(k0 + 2 * kp)     * HID + n0];
        float2 wo = *(const float2*)&Wrec[(k0 + 2 * kp + 1) * HID + n0];
        wr[kp * 2 + 0] = pack2(we.x, wo.x);
        wr[kp * 2 + 1] = pack2(we.y, wo.y);
    }
    // ---- Wih slice -> packed smem: [ks][ip][nj*2 + j] ----
#pragma unroll
    for (int ip = 0; ip < 4; ip++) {
        float2 we = *(const float2*)&Wih[(i0 + 2 * ip)     * HID + n0];
        float2 wo = *(const float2*)&Wih[(i0 + 2 * ip + 1) * HID + n0];
        wih_s[(ks * 4 + ip) * 64 + nj * 2 + 0] = pack2(we.x, wo.x);
        wih_s[(ks * 4 + ip) * 64 + nj * 2 + 1] = pack2(we.y, wo.y);
    }
    // Who o-slice transposed [o][k]
    for (int idx = t; idx < 8 * 512; idx += NTHR) {
        int ol = idx >> 9, k = idx & 511;
        who_s[ol * WHO_ROW + k] = Who[k * OUT_D + cs * 8 + ol];
    }
    // h0 = 0 in buffer 0; stage x[s=0] into x_s[0]
    for (int idx = t; idx < H_BUF; idx += NTHR) h_s[idx] = 0.0f;
    const int xrow = t >> 7, xcol = t & 127;
    x_s[0 * 512 + xrow * 128 + xcol] =
        x[((size_t)(g * 4 + xrow) * S_LEN) * IN_D + xcol];
    __syncthreads();

    // acc preloaded with x@Wih for step 0 (from x_s[0])
    ull acc[8];
#pragma unroll
    for (int q = 0; q < 8; q++) acc[q] = 0ull;
#pragma unroll
    for (int ip = 0; ip < 4; ip++) {
        ulonglong2 wv = *(const ulonglong2*)&wih_s[(ks * 4 + ip) * 64 + nj * 2];
#pragma unroll
        for (int b = 0; b < 4; b++) {
            float2 xv = *(const float2*)&x_s[0 * 512 + b * 128 + i0 + 2 * ip];
            ull xp = pack2(xv.x, xv.y);
            acc[b * 2 + 0] = fma2(xp, wv.x, acc[b * 2 + 0]);
            acc[b * 2 + 1] = fma2(xp, wv.y, acc[b * 2 + 1]);
        }
    }

#pragma unroll 1
    for (int s = 0; s < S_LEN; s++) {
        const int ph = s & 1, pn = ph ^ 1;
        const float* hb = h_s + ph * H_BUF;

        // prefetch next x (1 float/thread; retires under the GEMM)
        float xn = 0.0f;
        if (s + 1 < S_LEN)
            xn = x[((size_t)(g * 4 + xrow) * S_LEN + (s + 1)) * IN_D + xcol];

        // ---- critical GEMM: h@Wrec ONLY (x-part already in acc) ----
#pragma unroll
        for (int c = 0; c < 8; c++) {
            int kk = k0 + c * 4;
#pragma unroll
            for (int b = 0; b < 4; b++) {
                ulonglong2 h2 = *(const ulonglong2*)&hb[b * H_ROW + kk];  // broadcast
                acc[b * 2 + 0] = fma2(h2.x, wr[(c * 2) * 2 + 0],     acc[b * 2 + 0]);
                acc[b * 2 + 1] = fma2(h2.x, wr[(c * 2) * 2 + 1],     acc[b * 2 + 1]);
                acc[b * 2 + 0] = fma2(h2.y, wr[(c * 2 + 1) * 2 + 0], acc[b * 2 + 0]);
                acc[b * 2 + 1] = fma2(h2.y, wr[(c * 2 + 1) * 2 + 1], acc[b * 2 + 1]);
            }
        }
        // partials -> red[ks][b*64 + nj*2 + j]
#pragma unroll
        for (int b = 0; b < 4; b++) {
            float2 v;
            v.x = lo2(acc[b * 2 + 0]) + hi2(acc[b * 2 + 0]);
            v.y = lo2(acc[b * 2 + 1]) + hi2(acc[b * 2 + 1]);
            *(float2*)&red[ks * RED_ROW + b * 64 + nj * 2] = v;
        }
        // stage x[s+1] into next-parity buffer BEFORE S1 (visible after S1)
        x_s[pn * 512 + xrow * 128 + xcol] = xn;
        __syncthreads();                      // S1

        if (t < 256) {
            // ---- finalize (critical path) ----
            const int ob = t >> 6, oc = t & 63;
            float pre = 0.0f;
#pragma unroll
            for (int r = 0; r < 16; r++) pre += red[r * RED_ROW + ob * 64 + oc];
            float hold = hb[ob * H_ROW + cs * 64 + oc];
            float hnew = (1.0f - ALPHA) * hold + ALPHA * my_tanh(pre);
            g_hbuf[pn][(size_t)(g * 4 + ob) * HID + cs * 64 + oc] = hnew;
            asm volatile("bar.sync 1, 256;" ::: "memory");   // finalize warps only
            if (t == 0) rel_add1(cnt);                       // release
        }

        // ======== overlap window (h-independent) ========
        // preload acc with x@Wih for step s+1 (x_s[pn] visible via S1)
#pragma unroll
        for (int q = 0; q < 8; q++) acc[q] = 0ull;
        if (s + 1 < S_LEN) {
#pragma unroll
            for (int ip = 0; ip < 4; ip++) {
                ulonglong2 wv = *(const ulonglong2*)&wih_s[(ks * 4 + ip) * 64 + nj * 2];
#pragma unroll
                for (int b = 0; b < 4; b++) {
                    float2 xv = *(const float2*)&x_s[pn * 512 + b * 128 + i0 + 2 * ip];
                    ull xp = pack2(xv.x, xv.y);
                    acc[b * 2 + 0] = fma2(xp, wv.x, acc[b * 2 + 0]);
                    acc[b * 2 + 1] = fma2(xp, wv.y, acc[b * 2 + 1]);
                }
            }
        }
        // readout of previous step (reads current hb, untouched this phase)
        if (s) do_readout(hb, who_s, warp, lane, g, cs, s - 1, out);

        // ---- all-thread acquire poll (one L2 req per warp, broadcast line) ----
        {
            unsigned target = 8u * (unsigned)(s + 1);
            while (acq_ld(cnt) < target) { }
        }
        // stage h_{s+1} into next buffer via L1-bypass loads (16B/thread)
        {
            const float* g_h = g_hbuf[pn];
            float4 v = __ldcg((const float4*)&g_h[(size_t)g * 4 * HID + t * 4]);
            float* hn = h_s + pn * H_BUF;
            *(float4*)&hn[(t >> 7) * H_ROW + ((t * 4) & 511)] = v;
        }
        __syncthreads();                      // S3: staged h visible to all
    }

    // epilogue: h_2048 is in buffer 0 -> out row 2047
    do_readout(h_s, who_s, warp, lane, g, cs, S_LEN - 1, out);
}

extern "C" void kernel_launch(void* const* d_in, const int* in_sizes, int n_in,
                              void* d_out, int out_size) {
    const float* x    = (const float*)d_in[0];
    const float* Wih  = (const float*)d_in[1];
    const float* Wrec = (const float*)d_in[2];
    const float* Who  = (const float*)d_in[3];
    float* out = (float*)d_out;

    rnn_init_kernel<<<1, 32>>>();
    cudaFuncSetAttribute(rnn_v17_kernel,
                         cudaFuncAttributeMaxDynamicSharedMemorySize, SMEM_BYTES);
    rnn_v17_kernel<<<NGRP * NCS, NTHR, SMEM_BYTES>>>(x, Wih, Wrec, Who, out);
}